// round 17
// baseline (speedup 1.0000x reference)
#include <cuda_runtime.h>
#include <cuda_fp16.h>
#include <math.h>
#include <stdint.h>

#define SEQ 2048
#define HID 2048
#define NH 16
#define NKV 4
#define HD 128
#define QD (NH*HD)    /* 2048 */
#define KVD (NKV*HD)  /* 512  */

// Scratch (device globals: no allocations allowed)
__device__ uint32_t g_qt[SEQ*QD/2];          // fp16x2 Q (post-norm+rope)
__device__ uint32_t g_kt[SEQ*KVD/2];         // fp16x2 K (post-norm+rope)
__device__ uint32_t g_vt[KVD*SEQ/2];         // fp16x2 V, transposed [kvd][seq]
__device__ uint32_t g_o[SEQ*QD/2];           // attention output fp16x2
__device__ float2   g_rope[SEQ*64];
// Pre-converted fp16x2 operands (prepass); word = 2 k-consecutive elements
__device__ uint32_t g_xmu[SEQ*2*HID/2];      // [x | mu]  2048 x 2048 words
__device__ uint32_t g_wqc[QD*2*HID/2];
__device__ uint32_t g_wkc[KVD*2*HID/2];
__device__ uint32_t g_wvc[KVD*2*HID/2];
__device__ uint32_t g_wot[HID*QD/2];

// ---------------------------------------------------------------------------
// helpers
// ---------------------------------------------------------------------------
__device__ __forceinline__ uint32_t pack2h(float a, float b) {
    __half2 h = __floats2half2_rn(a, b);
    return *reinterpret_cast<uint32_t*>(&h);
}

__device__ __forceinline__ uint32_t ex2_h2(uint32_t a) {
    uint32_t r;
    asm("ex2.approx.f16x2 %0, %1;" : "=r"(r) : "r"(a));
    return r;
}

__device__ __forceinline__ void mma_f16(float d[4], const uint32_t a[4],
                                        uint32_t b0, uint32_t b1) {
    asm volatile(
        "mma.sync.aligned.m16n8k16.row.col.f32.f16.f16.f32 "
        "{%0,%1,%2,%3}, {%4,%5,%6,%7}, {%8,%9}, {%0,%1,%2,%3};"
        : "+f"(d[0]), "+f"(d[1]), "+f"(d[2]), "+f"(d[3])
        : "r"(a[0]), "r"(a[1]), "r"(a[2]), "r"(a[3]), "r"(b0), "r"(b1));
}

#define CP_ASYNC_CG(dst_u32, src_ptr) \
    asm volatile("cp.async.cg.shared.global [%0], [%1], 16;" :: "r"(dst_u32), "l"(src_ptr) : "memory")
#define CP_COMMIT() asm volatile("cp.async.commit_group;" ::: "memory")
#define CP_WAIT1()  asm volatile("cp.async.wait_group 1;"  ::: "memory")
#define CP_WAIT0()  asm volatile("cp.async.wait_group 0;"  ::: "memory")

__device__ __forceinline__ uint32_t smem_u32(const void* p) {
    uint32_t a;
    asm("{ .reg .u64 t; cvta.to.shared.u64 t, %1; cvt.u32.u64 %0, t; }" : "=r"(a) : "l"(p));
    return a;
}

// ---------------------------------------------------------------------------
// Fused prepass: fp32 -> fp16x2 (+K-concat). 8 elements -> 4 words per thread.
// ---------------------------------------------------------------------------
__global__ __launch_bounds__(256) void cvt_all(
    uint32_t* __restrict__ xmu, uint32_t* __restrict__ wqc,
    uint32_t* __restrict__ wkc, uint32_t* __restrict__ wvc,
    uint32_t* __restrict__ wot,
    const float* __restrict__ x,  const float* __restrict__ mu,
    const float* __restrict__ wq, const float* __restrict__ wmq,
    const float* __restrict__ wk, const float* __restrict__ wmk,
    const float* __restrict__ wv, const float* __restrict__ wmv,
    const float* __restrict__ wo)
{
    long e = ((long)blockIdx.x * 256 + threadIdx.x) * 8;
    const float *A, *B; uint32_t* D; long off; bool cat = true;
    if (e < 8388608L)       { D = xmu; A = x;  B = mu;  off = e; }
    else if (e < 16777216L) { D = wqc; A = wq; B = wmq; off = e - 8388608L; }
    else if (e < 18874368L) { D = wkc; A = wk; B = wmk; off = e - 16777216L; }
    else if (e < 20971520L) { D = wvc; A = wv; B = wmv; off = e - 18874368L; }
    else                    { D = wot; A = wo; B = wo;  off = e - 20971520L; cat = false; }

    const float* src;
    if (cat) {
        int r = (int)(off >> 12);
        int c = (int)(off & 4095);
        src = (c < 2048) ? (A + (size_t)r * 2048 + c) : (B + (size_t)r * 2048 + (c - 2048));
    } else {
        src = A + off;
    }
    float4 v0 = *(const float4*)src;
    float4 v1 = *(const float4*)(src + 4);
    *(uint4*)(D + (off >> 1)) = make_uint4(pack2h(v0.x, v0.y), pack2h(v0.z, v0.w),
                                           pack2h(v1.x, v1.y), pack2h(v1.z, v1.w));
}

// RoPE (cos,sin) table
__global__ __launch_bounds__(64) void rope_table(float2* __restrict__ tab)
{
    const int pos = blockIdx.x;
    const int f = threadIdx.x;
    float ang = (float)pos * powf(10000.0f, -(float)f * (1.0f / 64.0f));
    float sn, cs;
    sincosf(ang, &sn, &cs);
    tab[pos * 64 + f] = make_float2(cs, sn);
}

// ---------------------------------------------------------------------------
// cp.async 3-stage fp16 GEMM core (unchanged from R15).
// MODE 0: plain fp32 C. MODE 1: TRANSV fp16x2 transposed write (V).
// MODE 2: fused RMSNorm+RoPE epilogue -> fp16x2 (Q/K; col block == one head).
// ---------------------------------------------------------------------------
#define STG_WORDS 4096            /* 128*32 */
#define STAGE_WORDS (2*STG_WORDS)

template<int MODE>
__device__ __forceinline__ void gemm_core_async(
    const uint32_t* __restrict__ Ablk, const uint32_t* __restrict__ Bblk,
    float* __restrict__ Cblk, int ldc,
    uint32_t* __restrict__ Cth, int row0g, int col0g, int dstStrideW,
    const float* __restrict__ nw, const float2* __restrict__ rope,
    int Kelem, int ldaW, int ldbW, uint32_t* s)
{
    const uint32_t sbyte = smem_u32(s);
    const int tid = threadIdx.x;
    const int wid = tid >> 5, lane = tid & 31;
    const int g = lane >> 2, t = lane & 3;
    const int m0 = (wid >> 1) * 64;
    const int n0 = (wid & 1) * 64;

    const int lr = tid >> 3;
    const int ch = tid & 7;

    float acc[4][8][4];
#pragma unroll
    for (int i = 0; i < 4; ++i)
#pragma unroll
        for (int j = 0; j < 8; ++j)
#pragma unroll
            for (int q = 0; q < 4; ++q) acc[i][j][q] = 0.0f;

    const int nch = Kelem >> 6;
    const int chsw = ch ^ (lr & 7);

    auto issue = [&](int st, int cc) {
        const uint32_t sa0 = sbyte + (uint32_t)(st * STAGE_WORDS) * 4u;
        const uint32_t sb0 = sa0 + STG_WORDS * 4u;
        const int kkw = cc << 5;
#pragma unroll
        for (int i = 0; i < 8; ++i) {
            int r = lr + i * 16;
            uint32_t so = (uint32_t)(r * 32 + chsw * 4) * 4u;
            CP_ASYNC_CG(sa0 + so, Ablk + (size_t)r * ldaW + kkw + ch * 4);
            CP_ASYNC_CG(sb0 + so, Bblk + (size_t)r * ldbW + kkw + ch * 4);
        }
    };

    issue(0, 0); CP_COMMIT();
    issue(1, 1); CP_COMMIT();

    for (int c = 0; c < nch; ++c) {
        CP_WAIT1();
        __syncthreads();
        if (c + 2 < nch) issue((c + 2) % 3, c + 2);
        CP_COMMIT();

        const uint32_t* sA = s + (c % 3) * STAGE_WORDS;
        const uint32_t* sB = sA + STG_WORDS;
#pragma unroll
        for (int ks = 0; ks < 4; ++ks) {
            const int e1 = (((2 * ks) ^ g) << 2) + t;
            const int e2 = (((2 * ks) ^ g ^ 1) << 2) + t;
            uint32_t af[4][4], bf[8][2];
#pragma unroll
            for (int mt = 0; mt < 4; ++mt) {
                int mr = m0 + mt * 16 + g;
                af[mt][0] = sA[mr * 32 + e1];
                af[mt][1] = sA[(mr + 8) * 32 + e1];
                af[mt][2] = sA[mr * 32 + e2];
                af[mt][3] = sA[(mr + 8) * 32 + e2];
            }
#pragma unroll
            for (int nt = 0; nt < 8; ++nt) {
                int nr = n0 + nt * 8 + g;
                bf[nt][0] = sB[nr * 32 + e1];
                bf[nt][1] = sB[nr * 32 + e2];
            }
#pragma unroll
            for (int mt = 0; mt < 4; ++mt)
#pragma unroll
                for (int nt = 0; nt < 8; ++nt)
                    mma_f16(acc[mt][nt], af[mt], bf[nt][0], bf[nt][1]);
        }
    }

    if (MODE == 2) {
        __syncthreads();
        float* st = (float*)s;
        float* ssb = (float*)s + 128 * 132;

#pragma unroll
        for (int mt = 0; mt < 4; ++mt) {
            float s0 = 0.0f, s1 = 0.0f;
            int r0 = m0 + mt * 16 + g;
#pragma unroll
            for (int nt = 0; nt < 8; ++nt) {
                float a0 = acc[mt][nt][0], a1 = acc[mt][nt][1];
                float a2 = acc[mt][nt][2], a3 = acc[mt][nt][3];
                s0 += a0 * a0 + a1 * a1;
                s1 += a2 * a2 + a3 * a3;
                int cc = n0 + nt * 8 + 2 * t;
                *(float2*)&st[r0 * 132 + cc]       = make_float2(a0, a1);
                *(float2*)&st[(r0 + 8) * 132 + cc] = make_float2(a2, a3);
            }
            s0 += __shfl_xor_sync(0xffffffffu, s0, 1);
            s0 += __shfl_xor_sync(0xffffffffu, s0, 2);
            s1 += __shfl_xor_sync(0xffffffffu, s1, 1);
            s1 += __shfl_xor_sync(0xffffffffu, s1, 2);
            if (t == 0) {
                ssb[r0 * 2 + (wid & 1)]       = s0;
                ssb[(r0 + 8) * 2 + (wid & 1)] = s1;
            }
        }
        __syncthreads();

        const float sgn = (wid & 1) ? 1.0f : -1.0f;
#pragma unroll
        for (int mt = 0; mt < 4; ++mt) {
            int r0 = m0 + mt * 16 + g;
            int r1 = r0 + 8;
            float inv0 = rsqrtf((ssb[r0 * 2] + ssb[r0 * 2 + 1]) * (1.0f / 128.0f) + 1e-6f);
            float inv1 = rsqrtf((ssb[r1 * 2] + ssb[r1 * 2 + 1]) * (1.0f / 128.0f) + 1e-6f);
#pragma unroll
            for (int nt = 0; nt < 8; ++nt) {
                int cc = n0 + nt * 8 + 2 * t;
                int f = cc & 63;
                float w0 = nw[cc], w1 = nw[cc + 1];
                float wp0 = nw[cc ^ 64], wp1 = nw[(cc ^ 64) + 1];
                float2 cs0 = rope[(size_t)(row0g + r0) * 64 + f];
                float2 cs0b = rope[(size_t)(row0g + r0) * 64 + f + 1];
                float2 cs1 = rope[(size_t)(row0g + r1) * 64 + f];
                float2 cs1b = rope[(size_t)(row0g + r1) * 64 + f + 1];
                float2 p0 = *(const float2*)&st[r0 * 132 + (cc ^ 64)];
                float2 p1 = *(const float2*)&st[r1 * 132 + (cc ^ 64)];
                float o00 = acc[mt][nt][0] * inv0 * w0 * cs0.x  + sgn * p0.x * inv0 * wp0 * cs0.y;
                float o01 = acc[mt][nt][1] * inv0 * w1 * cs0b.x + sgn * p0.y * inv0 * wp1 * cs0b.y;
                float o10 = acc[mt][nt][2] * inv1 * w0 * cs1.x  + sgn * p1.x * inv1 * wp0 * cs1.y;
                float o11 = acc[mt][nt][3] * inv1 * w1 * cs1b.x + sgn * p1.y * inv1 * wp1 * cs1b.y;
                Cth[(size_t)(row0g + r0) * dstStrideW + (cc >> 1)] = pack2h(o00, o01);
                Cth[(size_t)(row0g + r1) * dstStrideW + (cc >> 1)] = pack2h(o10, o11);
            }
        }
        return;
    }

#pragma unroll
    for (int mt = 0; mt < 4; ++mt) {
        int r0 = m0 + mt * 16 + g;
#pragma unroll
        for (int nt = 0; nt < 8; ++nt) {
            int cc = n0 + nt * 8 + 2 * t;
            if (MODE == 1) {
                float p0 = acc[mt][nt][0], q0 = __shfl_xor_sync(0xffffffffu, p0, 4);
                float p1 = acc[mt][nt][1], q1 = __shfl_xor_sync(0xffffffffu, p1, 4);
                float p2 = acc[mt][nt][2], q2 = __shfl_xor_sync(0xffffffffu, p2, 4);
                float p3 = acc[mt][nt][3], q3 = __shfl_xor_sync(0xffffffffu, p3, 4);
                if (!(g & 1)) {
                    size_t w0 = (size_t)(col0g + cc)     * (SEQ / 2);
                    size_t w1 = (size_t)(col0g + cc + 1) * (SEQ / 2);
                    int rw0 = (row0g + r0) >> 1;
                    int rw1 = (row0g + r0 + 8) >> 1;
                    Cth[w0 + rw0] = pack2h(p0, q0);
                    Cth[w1 + rw0] = pack2h(p1, q1);
                    Cth[w0 + rw1] = pack2h(p2, q2);
                    Cth[w1 + rw1] = pack2h(p3, q3);
                }
            } else {
                *(float2*)(Cblk + (size_t)r0 * ldc + cc)       = make_float2(acc[mt][nt][0], acc[mt][nt][1]);
                *(float2*)(Cblk + (size_t)(r0 + 8) * ldc + cc) = make_float2(acc[mt][nt][2], acc[mt][nt][3]);
            }
        }
    }
}

// Fused QKV: grid (24, 16), 128 threads, all full K=4096.
__global__ __launch_bounds__(128, 2) void qkv_mma(
    const uint32_t* __restrict__ xmu,
    const uint32_t* __restrict__ wqc, const uint32_t* __restrict__ wkc,
    const uint32_t* __restrict__ wvc,
    uint32_t* __restrict__ pqt, uint32_t* __restrict__ pkt,
    uint32_t* __restrict__ pvt,
    const float* __restrict__ qw, const float* __restrict__ kw,
    const float2* __restrict__ rope)
{
    extern __shared__ uint32_t smem[];
    const int xb = blockIdx.x;
    const int row0 = blockIdx.y * 128;
    const uint32_t* A = xmu + (size_t)row0 * HID;

    if (xb < 4) {
        const int ccol = xb * 128;
        gemm_core_async<1>(A, wvc + (size_t)ccol * HID,
                           nullptr, 0, pvt, row0, ccol, 0, nullptr, nullptr,
                           2 * HID, HID, HID, smem);
    } else if (xb < 20) {
        const int head = xb - 4;
        gemm_core_async<2>(A, wqc + (size_t)(head * 128) * HID,
                           nullptr, 0, pqt + head * (HD / 2), row0, 0, QD / 2,
                           qw, rope, 2 * HID, HID, HID, smem);
    } else {
        const int head = xb - 20;
        gemm_core_async<2>(A, wkc + (size_t)(head * 128) * HID,
                           nullptr, 0, pkt + head * (HD / 2), row0, 0, KVD / 2,
                           kw, rope, 2 * HID, HID, HID, smem);
    }
}

// Output projection: grid = (16, 16), 128 threads
__global__ __launch_bounds__(128, 2) void oproj_mma(
    const uint32_t* __restrict__ A, const uint32_t* __restrict__ B, float* __restrict__ C)
{
    extern __shared__ uint32_t smem[];
    const int row0 = blockIdx.y * 128;
    const int ccol = blockIdx.x * 128;
    gemm_core_async<0>(A + (size_t)row0 * (QD / 2), B + (size_t)ccol * (QD / 2),
                       C + (size_t)row0 * QD + ccol, QD,
                       nullptr, 0, 0, 0, nullptr, nullptr,
                       QD, QD / 2, QD / 2, smem);
}

// ---------------------------------------------------------------------------
// fp16 causal flash attention. Q-tile 64 rows, 4 warps (128 thr), 3 CTAs/SM.
// grid = (SEQ/64, NH), reversed x (heavy first). P in registers, h2 exp.
// SMEM: 2 KV buffers only (32 KB each); Q staging ALIASES buffer 1 (buffer 1
// is first written at loop iter 0, after a full barrier that follows every
// thread's qf fragment load). Total 65536 B -> 3 CTAs/SM.
// ---------------------------------------------------------------------------
#define ATTN_SMEM_WORDS 16384

__global__ __launch_bounds__(128, 3) void attn_mma(
    const uint32_t* __restrict__ qt, const uint32_t* __restrict__ kt,
    const uint32_t* __restrict__ vt, uint32_t* __restrict__ o)
{
    extern __shared__ uint32_t sw[];
    uint32_t* sQ = sw + 8192;     // aliases KV buffer 1 (pre-loop only)
    const uint32_t sbyte = smem_u32(sw);

    const int qt_i = gridDim.x - 1 - blockIdx.x;   // heavy tiles first
    const int h = blockIdx.y;
    const int kvh = h >> 2;
    const int qrow0 = qt_i * 64;
    const int tid = threadIdx.x;
    const int w = tid >> 5, lane = tid & 31;
    const int gg = lane >> 2, t = lane & 3;
    const int m0 = w * 16;
    const int jmax = qt_i + 1;
    const int rmax = qrow0 + m0 + 15;

    auto issueKV = [&](int b, int jt) {
        const uint32_t kb0 = sbyte + (uint32_t)(b ? 8192 : 0) * 4u;
        const uint32_t vb0 = kb0 + 4096u * 4u;
#pragma unroll
        for (int i = 0; i < 8; ++i) {      // K: 64 rows x 16 chunks16
            int id = tid + i * 128;
            int r = id >> 4, c = id & 15;
            int cs = (c & 8) | ((c & 7) ^ (r & 7));
            CP_ASYNC_CG(kb0 + (uint32_t)(r * 64 + cs * 4) * 4u,
                        kt + (size_t)(jt * 64 + r) * (KVD / 2) + kvh * (HD / 2) + c * 4);
        }
#pragma unroll
        for (int i = 0; i < 8; ++i) {      // V: 128 rows x 8 chunks16
            int id = tid + i * 128;
            int r = id >> 3, c = id & 7;
            int cs = c ^ (r & 7);
            CP_ASYNC_CG(vb0 + (uint32_t)(r * 32 + cs * 4) * 4u,
                        vt + (size_t)(kvh * HD + r) * (SEQ / 2) + jt * 32 + c * 4);
        }
    };

    issueKV(0, 0); CP_COMMIT();

    // ---- stage Q into buffer-1 region (consumed before buffer 1 is written) ----
#pragma unroll
    for (int i = 0; i < 8; ++i) {
        int id = tid + i * 128;
        int r = id >> 4, w4 = (id & 15) << 2;
        uint4 v = *(const uint4*)(qt + (size_t)(qrow0 + r) * (QD / 2) + h * (HD / 2) + w4);
        sQ[r * 68 + w4 + 0] = v.x;
        sQ[r * 68 + w4 + 1] = v.y;
        sQ[r * 68 + w4 + 2] = v.z;
        sQ[r * 68 + w4 + 3] = v.w;
    }
    __syncthreads();

    uint32_t qf[8][4];
#pragma unroll
    for (int ks = 0; ks < 8; ++ks) {
        qf[ks][0] = sQ[(m0 + gg) * 68 + ks * 8 + t];
        qf[ks][1] = sQ[(m0 + gg + 8) * 68 + ks * 8 + t];
        qf[ks][2] = sQ[(m0 + gg) * 68 + ks * 8 + 4 + t];
        qf[ks][3] = sQ[(m0 + gg + 8) * 68 + ks * 8 + 4 + t];
    }

    float oacc[16][4];
#pragma unroll
    for (int i = 0; i < 16; ++i)
#pragma unroll
        for (int j = 0; j < 4; ++j) oacc[i][j] = 0.0f;
    float mrow0 = -1e30f, mrow1 = -1e30f, lrow0 = 0.0f, lrow1 = 0.0f;

    const float scale = 0.08838834764831845f;
    const float L2E = 1.4426950408889634f;

    for (int jt = 0; jt < jmax; ++jt) {
        CP_WAIT0();
        __syncthreads();   // all qf loads done (iter 0) / all compute done (iter >0)
        if (jt + 1 < jmax) { issueKV((jt + 1) & 1, jt + 1); CP_COMMIT(); }

        const uint32_t* sK = sw + ((jt & 1) ? 8192 : 0);
        const uint32_t* sV = sK + 4096;

        const bool edge = (jt == qt_i);

        float sacc[8][4];
#pragma unroll
        for (int i = 0; i < 8; ++i)
#pragma unroll
            for (int j = 0; j < 4; ++j) sacc[i][j] = 0.0f;

        if (!edge) {
#pragma unroll
            for (int ks = 0; ks < 8; ++ks) {
                const int c0 = (((2 * ks) & 8) | (((2 * ks) & 7) ^ gg)) * 4 + t;
                const int c1 = (((2 * ks + 1) & 8) | (((2 * ks + 1) & 7) ^ gg)) * 4 + t;
#pragma unroll
                for (int nt = 0; nt < 8; ++nt) {
                    int nr = nt * 8 + gg;
                    mma_f16(sacc[nt], qf[ks], sK[nr * 64 + c0], sK[nr * 64 + c1]);
                }
            }
        } else {
#pragma unroll
            for (int nt = 0; nt < 8; ++nt) {
                if (jt * 64 + nt * 8 <= rmax) {
                    const int nr = nt * 8 + gg;
#pragma unroll
                    for (int ks = 0; ks < 8; ++ks) {
                        const int c0 = (((2 * ks) & 8) | (((2 * ks) & 7) ^ gg)) * 4 + t;
                        const int c1 = (((2 * ks + 1) & 8) | (((2 * ks + 1) & 7) ^ gg)) * 4 + t;
                        mma_f16(sacc[nt], qf[ks], sK[nr * 64 + c0], sK[nr * 64 + c1]);
                    }
                }
            }
        }

        const int r0 = qrow0 + m0 + gg;
        const int r1 = r0 + 8;
        float rm0 = -1e30f, rm1 = -1e30f;
#pragma unroll
        for (int nt = 0; nt < 8; ++nt) {
            float c0 = sacc[nt][0] * scale, c1 = sacc[nt][1] * scale;
            float c2 = sacc[nt][2] * scale, c3 = sacc[nt][3] * scale;
            if (edge) {
                int colb = jt * 64 + nt * 8 + 2 * t;
                if (colb     > r0) c0 = -1e30f;
                if (colb + 1 > r0) c1 = -1e30f;
                if (colb     > r1) c2 = -1e30f;
                if (colb + 1 > r1) c3 = -1e30f;
            }
            sacc[nt][0] = c0; sacc[nt][1] = c1; sacc[nt][2] = c2; sacc[nt][3] = c3;
            rm0 = fmaxf(rm0, fmaxf(c0, c1));
            rm1 = fmaxf(rm1, fmaxf(c2, c3));
        }
        rm0 = fmaxf(rm0, __shfl_xor_sync(0xffffffffu, rm0, 1));
        rm0 = fmaxf(rm0, __shfl_xor_sync(0xffffffffu, rm0, 2));
        rm1 = fmaxf(rm1, __shfl_xor_sync(0xffffffffu, rm1, 1));
        rm1 = fmaxf(rm1, __shfl_xor_sync(0xffffffffu, rm1, 2));

        float mn0 = fmaxf(mrow0, rm0), mn1 = fmaxf(mrow1, rm1);
        float al0 = __expf(mrow0 - mn0), al1 = __expf(mrow1 - mn1);
        mrow0 = mn0; mrow1 = mn1;

        const float mn0L = mn0 * L2E, mn1L = mn1 * L2E;
        uint32_t pu[8][2];
        float rs0 = 0.0f, rs1 = 0.0f;
#pragma unroll
        for (int nt = 0; nt < 8; ++nt) {
            uint32_t a0 = pack2h(fmaf(sacc[nt][0], L2E, -mn0L),
                                 fmaf(sacc[nt][1], L2E, -mn0L));
            uint32_t a1 = pack2h(fmaf(sacc[nt][2], L2E, -mn1L),
                                 fmaf(sacc[nt][3], L2E, -mn1L));
            pu[nt][0] = ex2_h2(a0);
            pu[nt][1] = ex2_h2(a1);
            float2 f0 = __half22float2(*reinterpret_cast<__half2*>(&pu[nt][0]));
            float2 f1 = __half22float2(*reinterpret_cast<__half2*>(&pu[nt][1]));
            rs0 += f0.x + f0.y;
            rs1 += f1.x + f1.y;
        }
        rs0 += __shfl_xor_sync(0xffffffffu, rs0, 1);
        rs0 += __shfl_xor_sync(0xffffffffu, rs0, 2);
        rs1 += __shfl_xor_sync(0xffffffffu, rs1, 1);
        rs1 += __shfl_xor_sync(0xffffffffu, rs1, 2);
        lrow0 = lrow0 * al0 + rs0;
        lrow1 = lrow1 * al1 + rs1;

#pragma unroll
        for (int nt = 0; nt < 16; ++nt) {
            oacc[nt][0] *= al0; oacc[nt][1] *= al0;
            oacc[nt][2] *= al1; oacc[nt][3] *= al1;
        }

#pragma unroll
        for (int ks = 0; ks < 4; ++ks) {
            if (edge && (jt * 64 + ks * 16 > rmax)) continue;
            uint32_t a[4] = {pu[2 * ks][0], pu[2 * ks][1],
                             pu[2 * ks + 1][0], pu[2 * ks + 1][1]};
            const int c0 = (((2 * ks) ^ gg) & 7) * 4 + t;
            const int c1 = (((2 * ks + 1) ^ gg) & 7) * 4 + t;
#pragma unroll
            for (int nt = 0; nt < 16; ++nt) {
                int nr = nt * 8 + gg;
                mma_f16(oacc[nt], a, sV[nr * 32 + c0], sV[nr * 32 + c1]);
            }
        }
    }

    const float inv0 = 1.0f / lrow0, inv1 = 1.0f / lrow1;
    const int r0 = qrow0 + m0 + gg;
#pragma unroll
    for (int nt = 0; nt < 16; ++nt) {
        int wi = h * (HD / 2) + nt * 4 + t;
        o[(size_t)r0 * (QD / 2) + wi]       = pack2h(oacc[nt][0] * inv0, oacc[nt][1] * inv0);
        o[(size_t)(r0 + 8) * (QD / 2) + wi] = pack2h(oacc[nt][2] * inv1, oacc[nt][3] * inv1);
    }
}

// ---------------------------------------------------------------------------
extern "C" void kernel_launch(void* const* d_in, const int* in_sizes, int n_in,
                              void* d_out, int out_size)
{
    (void)in_sizes; (void)n_in; (void)out_size;
    const float* x   = (const float*)d_in[0];
    const float* mu  = (const float*)d_in[1];
    const float* wq  = (const float*)d_in[2];
    const float* wk  = (const float*)d_in[3];
    const float* wv  = (const float*)d_in[4];
    const float* wo  = (const float*)d_in[5];
    const float* wmq = (const float*)d_in[6];
    const float* wmk = (const float*)d_in[7];
    const float* wmv = (const float*)d_in[8];
    const float* qw  = (const float*)d_in[9];
    const float* kw  = (const float*)d_in[10];
    float* out = (float*)d_out;

    uint32_t *pqt, *pkt, *pvt, *po;
    uint32_t *pxmu, *pwqc, *pwkc, *pwvc, *pwot;
    float2 *prope;
    cudaGetSymbolAddress((void**)&pqt, g_qt);
    cudaGetSymbolAddress((void**)&pkt, g_kt);
    cudaGetSymbolAddress((void**)&pvt, g_vt);
    cudaGetSymbolAddress((void**)&po, g_o);
    cudaGetSymbolAddress((void**)&pxmu, g_xmu);
    cudaGetSymbolAddress((void**)&pwqc, g_wqc);
    cudaGetSymbolAddress((void**)&pwkc, g_wkc);
    cudaGetSymbolAddress((void**)&pwvc, g_wvc);
    cudaGetSymbolAddress((void**)&pwot, g_wot);
    cudaGetSymbolAddress((void**)&prope, g_rope);

    // ---- fused prepass ----
    rope_table<<<SEQ, 64>>>(prope);
    cvt_all<<<12288, 256>>>(pxmu, pwqc, pwkc, pwvc, pwot,
                            x, mu, wq, wmq, wk, wmk, wv, wmv, wo);

    const int gemm_smem = 3 * STAGE_WORDS * 4;  // 98304 bytes
    cudaFuncSetAttribute(qkv_mma,   cudaFuncAttributeMaxDynamicSharedMemorySize, gemm_smem);
    cudaFuncSetAttribute(oproj_mma, cudaFuncAttributeMaxDynamicSharedMemorySize, gemm_smem);

    // Fused QKV + RMSNorm + RoPE (Q/K) + V transpose, all fp16 outputs
    qkv_mma<<<dim3(24, 16), 128, gemm_smem>>>(pxmu, pwqc, pwkc, pwvc,
                                              pqt, pkt, pvt, qw, kw, prope);

    // causal GQA attention (fp16 mma, 64-row Q tiles, 3 CTAs/SM)
    const int attn_smem = ATTN_SMEM_WORDS * 4;  // 65536 bytes
    cudaFuncSetAttribute(attn_mma, cudaFuncAttributeMaxDynamicSharedMemorySize, attn_smem);
    attn_mma<<<dim3(SEQ / 64, NH), 128, attn_smem>>>(pqt, pkt, pvt, po);

    // output projection (fp16 mma)
    oproj_mma<<<dim3(16, 16), 128, gemm_smem>>>(po, pwot, out);
}